// round 17
// baseline (speedup 1.0000x reference)
#include <cuda_runtime.h>
#include <cuda_fp16.h>
#include <cstdint>

#define NV 4096
#define ALPHA 0.2f

// ---------------- device scratch ----------------
__device__ float g_e1[NV], g_e2[NV];
__device__ float g_E1[NV], g_E2[NV];
__device__ float g_A[NV], g_B[NV], g_thE[NV], g_dinv[NV];
__device__ float g_part[4][NV * 64];
__device__ float g_pWh[4][256 * 1024];   // k-split partials of Wh
// fragment-ordered B: [jt 0..255][n 0..7][reg 0..1][lane 0..31], u32 = f16x2
__device__ uint32_t g_WhB[256 * 512];
__device__ int g_cnt[128];
__device__ int g_cntW[256];

// ---------------- K1: split-k Wh partials + finisher epilogue ----------------
// Grid 1024 = 256 j-tiles x 4 k-chunks. Each CTA: 16 rows x 64 k partial.
// 4th arriving CTA per j-tile combines, computes e1/e2/E1/E2, emits fragments.
__global__ __launch_bounds__(256) void k1_wh(const float* __restrict__ H,
                                             const float* __restrict__ W,
                                             const float* __restrict__ a) {
    __shared__ float Ws[64][64];      // 16 KB
    __shared__ float Hs[16][68];      // 4.25 KB
    __shared__ float t[16][68];       // 4.25 KB
    __shared__ int s_fin;
    int tid = threadIdx.x;
    int tr = tid >> 4;
    int tc = tid & 15;
    int jt = blockIdx.x >> 2;
    int ks = blockIdx.x & 3;
    int row0 = jt * 16;
    int k0 = ks * 64;

    // stage W chunk (64x64) and H tile (16x64)
#pragma unroll
    for (int q = 0; q < 4; q++) {
        int u = tid + q * 256;
        int r = u >> 4, c4 = u & 15;
        *(float4*)&Ws[r][c4 * 4] = *(const float4*)&W[(size_t)(k0 + r) * 64 + c4 * 4];
    }
    *(float4*)&Hs[tr][tc * 4] = *(const float4*)&H[(size_t)(row0 + tr) * 256 + k0 + tc * 4];
    __syncthreads();

    unsigned long long acc[2][2] = {{0ull, 0ull}, {0ull, 0ull}};
#pragma unroll 8
    for (int k = 0; k < 64; k++) {
        float4 w4 = *(const float4*)&Ws[k][tc * 4];
        unsigned long long w01, w23, hp;
        asm("mov.b64 %0, {%1, %2};" : "=l"(w01) : "f"(w4.x), "f"(w4.y));
        asm("mov.b64 %0, {%1, %2};" : "=l"(w23) : "f"(w4.z), "f"(w4.w));
        float h = Hs[tr][k];
        asm("mov.b64 %0, {%1, %1};" : "=l"(hp) : "f"(h));
        int p = k & 1;
        asm("fma.rn.f32x2 %0, %1, %2, %0;" : "+l"(acc[p][0]) : "l"(hp), "l"(w01));
        asm("fma.rn.f32x2 %0, %1, %2, %0;" : "+l"(acc[p][1]) : "l"(hp), "l"(w23));
    }
    float v0 = __uint_as_float((uint32_t)acc[0][0]) + __uint_as_float((uint32_t)acc[1][0]);
    float v1 = __uint_as_float((uint32_t)(acc[0][0] >> 32)) + __uint_as_float((uint32_t)(acc[1][0] >> 32));
    float v2 = __uint_as_float((uint32_t)acc[0][1]) + __uint_as_float((uint32_t)acc[1][1]);
    float v3 = __uint_as_float((uint32_t)(acc[0][1] >> 32)) + __uint_as_float((uint32_t)(acc[1][1] >> 32));

    // store partial plane
    *(float4*)&g_pWh[ks][(size_t)jt * 1024 + tid * 4] = make_float4(v0, v1, v2, v3);

    __threadfence();
    __syncthreads();
    if (tid == 0) {
        int old = atomicAdd(&g_cntW[jt], 1);
        s_fin = (old == 3);
    }
    __syncthreads();
    if (!s_fin) return;
    __threadfence();

    // ---- finisher: combine 4 partials ----
    size_t poff = (size_t)jt * 1024 + tid * 4;
    float4 s0 = *(const float4*)&g_pWh[0][poff];
    float4 s1 = *(const float4*)&g_pWh[1][poff];
    float4 s2 = *(const float4*)&g_pWh[2][poff];
    float4 s3 = *(const float4*)&g_pWh[3][poff];
    v0 = s0.x + s1.x + s2.x + s3.x;
    v1 = s0.y + s1.y + s2.y + s3.y;
    v2 = s0.z + s1.z + s2.z + s3.z;
    v3 = s0.w + s1.w + s2.w + s3.w;

    *(float4*)&t[tr][tc * 4] = make_float4(v0, v1, v2, v3);

    int i = row0 + tr;
    float p1 = v0 * __ldg(&a[tc * 4]) + v1 * __ldg(&a[tc * 4 + 1])
             + v2 * __ldg(&a[tc * 4 + 2]) + v3 * __ldg(&a[tc * 4 + 3]);
    float p2 = v0 * __ldg(&a[64 + tc * 4]) + v1 * __ldg(&a[64 + tc * 4 + 1])
             + v2 * __ldg(&a[64 + tc * 4 + 2]) + v3 * __ldg(&a[64 + tc * 4 + 3]);
#pragma unroll
    for (int off = 1; off < 16; off <<= 1) {
        p1 += __shfl_xor_sync(0xffffffffu, p1, off);
        p2 += __shfl_xor_sync(0xffffffffu, p2, off);
    }
    if (tc == 0) {
        g_e1[i] = p1;
        g_e2[i] = p2;
        g_E1[i] = __expf(p2);
        g_E2[i] = __expf(ALPHA * p2);
    }
    __syncthreads();

    // emit fp16 B fragments for this j-tile
#pragma unroll
    for (int q = 0; q < 2; q++) {
        int idx = tid + q * 256;
        int lane = idx & 31;
        int reg = (idx >> 5) & 1;
        int n = idx >> 6;
        int gid2 = lane >> 2, tg2 = lane & 3;
        int jr = tg2 * 2 + reg * 8;
        int c = n * 8 + gid2;
        __half2 h = __floats2half2_rn(t[jr][c], t[jr + 1][c]);
        g_WhB[(size_t)jt * 512 + idx] = *(uint32_t*)&h;
    }
    if (tid == 0) g_cntW[jt] = 0;   // self-reset for next graph replay
}

// ---------------- K2: per-row denominator (+ k3 counter reset) ---------------
__global__ __launch_bounds__(256) void k2_denom() {
    __shared__ float sE1[NV];
    __shared__ float sE2[NV];
    __shared__ float red[8];
    int tid = threadIdx.x;
    int warp = tid >> 5, lane = tid & 31;
    if (blockIdx.x < 128 && tid == 0) g_cnt[blockIdx.x] = 0;
#pragma unroll
    for (int t = 0; t < 4; t++) {
        ((float4*)sE1)[tid + t * 256] = __ldg(&((const float4*)g_E1)[tid + t * 256]);
        ((float4*)sE2)[tid + t * 256] = __ldg(&((const float4*)g_E2)[tid + t * 256]);
    }
    float mx = -1e30f;
#pragma unroll
    for (int t = 0; t < 4; t++) {
        float4 v = __ldg(&((const float4*)g_e2)[tid + t * 256]);
        mx = fmaxf(fmaxf(mx, v.x), fmaxf(fmaxf(v.y, v.z), v.w));
    }
#pragma unroll
    for (int o = 16; o > 0; o >>= 1) mx = fmaxf(mx, __shfl_xor_sync(0xffffffffu, mx, o));
    if (lane == 0) red[warp] = mx;
    __syncthreads();
    float e2max = red[0];
#pragma unroll
    for (int w = 1; w < 8; w++) e2max = fmaxf(e2max, red[w]);

    int i = blockIdx.x * 8 + warp;
    float e1v = g_e1[i];
    float s = e1v + e2max;
    float m = s > 0.f ? s : ALPHA * s;
    float A = __expf(e1v - m);
    float B = __expf(ALPHA * e1v - m);
    float thE = __expf(-e1v);

    float d = 0.f;
#pragma unroll 8
    for (int t = 0; t < 32; t++) {
        int j = (lane + t * 32) * 4;
        float4 E1v = *(const float4*)&sE1[j];
        float4 E2v = *(const float4*)&sE2[j];
        d += (E1v.x > thE) ? A * E1v.x : B * E2v.x;
        d += (E1v.y > thE) ? A * E1v.y : B * E2v.y;
        d += (E1v.z > thE) ? A * E1v.z : B * E2v.z;
        d += (E1v.w > thE) ? A * E1v.w : B * E2v.w;
    }
#pragma unroll
    for (int o = 16; o > 0; o >>= 1) d += __shfl_xor_sync(0xffffffffu, d, o);
    if (lane == 0) {
        g_A[i] = A; g_B[i] = B; g_thE[i] = thE;
        g_dinv[i] = 1.f / d;
    }
}

// ---------------- A-fragment build ----------------
__device__ __forceinline__ uint32_t build_a(int ax, int ay,
                                            float e1x, float e1y,
                                            float e2x, float e2y,
                                            float Ai, float Bi, float th) {
    float w0 = (ax > 0) ? ((e1x > th) ? Ai * e1x : Bi * e2x) : 0.f;
    float w1 = (ay > 0) ? ((e1y > th) ? Ai * e1y : Bi * e2y) : 0.f;
    __half2 h = __floats2half2_rn(w0, w1);
    return *(uint32_t*)&h;
}

#define MMA_F16(c0, c1, c2, c3, a0, a1, a2, a3, b0, b1)                         \
    asm("mma.sync.aligned.m16n8k16.row.col.f32.f16.f16.f32 "                   \
        "{%0,%1,%2,%3}, {%4,%5,%6,%7}, {%8,%9}, {%0,%1,%2,%3};"                \
        : "+f"(c0), "+f"(c1), "+f"(c2), "+f"(c3)                               \
        : "r"(a0), "r"(a1), "r"(a2), "r"(a3), "r"(b0), "r"(b1))

#define CP_WAIT(n) asm volatile("cp.async.wait_group %0;" :: "n"(n) : "memory")

// ---------------- K3: masked GEMM + fused final reduce/ELU -------------------
__global__ __launch_bounds__(128, 4) void k3_main(const int* __restrict__ adj,
                                                  float* __restrict__ out) {
    __shared__ union {
        struct {
            int adjt[4][3][640];
            float E1[4][256];
            float E2[4][256];
        } a;
        float red[4][32][68];
    } su;
    __shared__ int s_last;

    int tid = threadIdx.x;
    int warp = tid >> 5, lane = tid & 31;
    int gid = lane >> 2, tg = lane & 3;
    int rb = blockIdx.x >> 2;
    int jseg = blockIdx.x & 3;
    int jq = jseg * 1024 + warp * 256;
    int base = rb * 32;

    const int* adjw = adj + (size_t)base * NV + jq;
    int cp_row = lane >> 2;
    int cp_part = lane & 3;

#pragma unroll
    for (int kt = 0; kt < 3; kt++) {
#pragma unroll
        for (int q = 0; q < 4; q++) {
            int row = cp_row + q * 8;
            unsigned daddr = (unsigned)__cvta_generic_to_shared(
                &su.a.adjt[warp][kt][row * 20 + cp_part * 4]);
            const int* src = adjw + (size_t)row * NV + kt * 16 + cp_part * 4;
            asm volatile("cp.async.cg.shared.global [%0], [%1], 16;"
                         :: "r"(daddr), "l"(src) : "memory");
        }
        asm volatile("cp.async.commit_group;" ::: "memory");
    }

#pragma unroll
    for (int t = 0; t < 2; t++) {
        int idx = lane + t * 32;
        float4 v1 = __ldg(&((const float4*)(g_E1 + jq))[idx]);
        *(float4*)&su.a.E1[warp][idx * 4] = v1;
        float4 v2 = __ldg(&((const float4*)(g_E2 + jq))[idx]);
        *(float4*)&su.a.E2[warp][idx * 4] = v2;
    }
    __syncwarp();

    int r0 = base + gid, r1 = r0 + 8, r2 = r0 + 16, r3 = r0 + 24;
    float Ai0 = __ldg(&g_A[r0]), Bi0 = __ldg(&g_B[r0]), th0 = __ldg(&g_thE[r0]);
    float Ai1 = __ldg(&g_A[r1]), Bi1 = __ldg(&g_B[r1]), th1 = __ldg(&g_thE[r1]);
    float Ai2 = __ldg(&g_A[r2]), Bi2 = __ldg(&g_B[r2]), th2 = __ldg(&g_thE[r2]);
    float Ai3 = __ldg(&g_A[r3]), Bi3 = __ldg(&g_B[r3]), th3 = __ldg(&g_thE[r3]);

    float acc[2][8][4];
#pragma unroll
    for (int m = 0; m < 2; m++)
#pragma unroll
        for (int n = 0; n < 8; n++)
#pragma unroll
            for (int q = 0; q < 4; q++) acc[m][n][q] = 0.f;

    int jt0 = jq >> 4;

#pragma unroll
    for (int kt = 0; kt < 16; ++kt) {
        uint32_t b0[8], b1[8];
        const uint32_t* bb = g_WhB + (size_t)(jt0 + kt) * 512 + lane;
#pragma unroll
        for (int n = 0; n < 8; n++) {
            b0[n] = __ldg(bb + n * 64);
            b1[n] = __ldg(bb + n * 64 + 32);
        }

        if (kt <= 13) { CP_WAIT(2); } else if (kt == 14) { CP_WAIT(1); } else { CP_WAIT(0); }
        __syncwarp();

        const int* sa = su.a.adjt[warp][kt % 3];
        int2 c0a = *(const int2*)&sa[gid * 20 + tg * 2];
        int2 c0b = *(const int2*)&sa[gid * 20 + tg * 2 + 8];
        int2 c1a = *(const int2*)&sa[(gid + 8) * 20 + tg * 2];
        int2 c1b = *(const int2*)&sa[(gid + 8) * 20 + tg * 2 + 8];
        int2 c2a = *(const int2*)&sa[(gid + 16) * 20 + tg * 2];
        int2 c2b = *(const int2*)&sa[(gid + 16) * 20 + tg * 2 + 8];
        int2 c3a = *(const int2*)&sa[(gid + 24) * 20 + tg * 2];
        int2 c3b = *(const int2*)&sa[(gid + 24) * 20 + tg * 2 + 8];

        int j0 = kt * 16 + tg * 2;
        float2 e10 = *(const float2*)&su.a.E1[warp][(j0 & 255)];
        float2 e18 = *(const float2*)&su.a.E1[warp][((j0 + 8) & 255)];
        float2 e20 = *(const float2*)&su.a.E2[warp][(j0 & 255)];
        float2 e28 = *(const float2*)&su.a.E2[warp][((j0 + 8) & 255)];

        uint32_t ah[2][4];
        ah[0][0] = build_a(c0a.x, c0a.y, e10.x, e10.y, e20.x, e20.y, Ai0, Bi0, th0);
        ah[0][1] = build_a(c1a.x, c1a.y, e10.x, e10.y, e20.x, e20.y, Ai1, Bi1, th1);
        ah[0][2] = build_a(c0b.x, c0b.y, e18.x, e18.y, e28.x, e28.y, Ai0, Bi0, th0);
        ah[0][3] = build_a(c1b.x, c1b.y, e18.x, e18.y, e28.x, e28.y, Ai1, Bi1, th1);
        ah[1][0] = build_a(c2a.x, c2a.y, e10.x, e10.y, e20.x, e20.y, Ai2, Bi2, th2);
        ah[1][1] = build_a(c3a.x, c3a.y, e10.x, e10.y, e20.x, e20.y, Ai3, Bi3, th3);
        ah[1][2] = build_a(c2b.x, c2b.y, e18.x, e18.y, e28.x, e28.y, Ai2, Bi2, th2);
        ah[1][3] = build_a(c3b.x, c3b.y, e18.x, e18.y, e28.x, e28.y, Ai3, Bi3, th3);

        if (kt < 13) {
            int ktn = kt + 3;
#pragma unroll
            for (int q = 0; q < 4; q++) {
                int row = cp_row + q * 8;
                unsigned daddr = (unsigned)__cvta_generic_to_shared(
                    &su.a.adjt[warp][kt % 3][row * 20 + cp_part * 4]);
                const int* src = adjw + (size_t)row * NV + ktn * 16 + cp_part * 4;
                asm volatile("cp.async.cg.shared.global [%0], [%1], 16;"
                             :: "r"(daddr), "l"(src) : "memory");
            }
            asm volatile("cp.async.commit_group;" ::: "memory");
        }

#pragma unroll
        for (int n = 0; n < 8; n++) {
#pragma unroll
            for (int m = 0; m < 2; m++) {
                MMA_F16(acc[m][n][0], acc[m][n][1], acc[m][n][2], acc[m][n][3],
                        ah[m][0], ah[m][1], ah[m][2], ah[m][3], b0[n], b1[n]);
            }
        }
    }

    // ---- cross-warp reduction ----
    __syncthreads();
    float* sw = &su.red[warp][0][0];
#pragma unroll
    for (int n = 0; n < 8; n++) {
        int c = n * 8 + tg * 2;
        *(float2*)&sw[gid * 68 + c]        = make_float2(acc[0][n][0], acc[0][n][1]);
        *(float2*)&sw[(gid + 8) * 68 + c]  = make_float2(acc[0][n][2], acc[0][n][3]);
        *(float2*)&sw[(gid + 16) * 68 + c] = make_float2(acc[1][n][0], acc[1][n][1]);
        *(float2*)&sw[(gid + 24) * 68 + c] = make_float2(acc[1][n][2], acc[1][n][3]);
    }
    __syncthreads();

    float* dst = g_part[jseg];
#pragma unroll
    for (int q = 0; q < 4; q++) {
        int v = tid + q * 128;
        int row = v >> 4;
        int col = (v & 15) * 4;
        float4 s0 = *(const float4*)&su.red[0][row][col];
        float4 s1 = *(const float4*)&su.red[1][row][col];
        float4 s2 = *(const float4*)&su.red[2][row][col];
        float4 s3 = *(const float4*)&su.red[3][row][col];
        float4 r;
        r.x = s0.x + s1.x + s2.x + s3.x;
        r.y = s0.y + s1.y + s2.y + s3.y;
        r.z = s0.z + s1.z + s2.z + s3.z;
        r.w = s0.w + s1.w + s2.w + s3.w;
        *(float4*)&dst[(size_t)(base + row) * 64 + col] = r;
    }

    // ---- fused final pass ----
    __threadfence();
    __syncthreads();
    if (tid == 0) {
        int old = atomicAdd(&g_cnt[rb], 1);
        s_last = (old == 3);
    }
    __syncthreads();
    if (s_last) {
        __threadfence();
#pragma unroll
        for (int q = 0; q < 4; q++) {
            int v = tid + q * 128;
            int row = v >> 4;
            int col = (v & 15) * 4;
            size_t off = (size_t)(base + row) * 64 + col;
            float4 s = *(const float4*)&g_part[0][off];
            float4 t1 = *(const float4*)&g_part[1][off];
            float4 t2 = *(const float4*)&g_part[2][off];
            float4 t3 = *(const float4*)&g_part[3][off];
            s.x += t1.x + t2.x + t3.x;
            s.y += t1.y + t2.y + t3.y;
            s.z += t1.z + t2.z + t3.z;
            s.w += t1.w + t2.w + t3.w;
            float di = g_dinv[base + row];
            s.x *= di; s.y *= di; s.z *= di; s.w *= di;
            s.x = s.x > 0.f ? s.x : (__expf(s.x) - 1.f);
            s.y = s.y > 0.f ? s.y : (__expf(s.y) - 1.f);
            s.z = s.z > 0.f ? s.z : (__expf(s.z) - 1.f);
            s.w = s.w > 0.f ? s.w : (__expf(s.w) - 1.f);
            *(float4*)&out[off] = s;
        }
    }
}

// ---------------- launch ----------------
extern "C" void kernel_launch(void* const* d_in, const int* in_sizes, int n_in,
                              void* d_out, int out_size) {
    const float* H = (const float*)d_in[0];
    const int* adj = (const int*)d_in[1];
    const float* W = (const float*)d_in[2];
    const float* a = (const float*)d_in[3];
    float* out = (float*)d_out;

    k1_wh<<<1024, 256>>>(H, W, a);
    k2_denom<<<512, 256>>>();
    k3_main<<<512, 128>>>(adj, out);
}